// round 13
// baseline (speedup 1.0000x reference)
#include <cuda_runtime.h>
#include <cuda_bf16.h>
#include <math.h>

// Problem constants
#define T_STEPS 256
#define BATCH   64
#define DIN     512
#define HID     1024
#define DH      (DIN + HID)       // 1536
#define NG      (4 * HID)         // 4096
#define M1      (T_STEPS * BATCH) // 16384

#define GRID_P  128               // persistent blocks
#define THR_R   512               // 16 warps (recurrence)
#define JPB     8                 // j-units per block
#define CPB     32                // gate-columns per block

// ---- LSTM SMEM layout (bytes) ------------------------------------------------
#define WPAD     1032              // bf16 Whi row stride (elems)
#define SM_WHI   0                 // 32 x 1032 x 2 = 66048
#define W8PAD    2080              // int8 corr-W row stride (bytes)
#define SM_W8    66048             // 32 x 2080 = 66560 -> end 132608
#define SM_A0    132608            // chunk buf: A_hi bf16 [64][136] (17408B) + A8 [64][272]
#define A8OFF    17408
#define A8PAD    272               // also the A_hi byte row stride (136*2)
#define ABUF     34816
#define SM_A1    (SM_A0 + ABUF)    // 167424
#define SMEM_TOTAL (SM_A1 + ABUF)  // 202240
#define SM_D     SM_A0             // D: 256 rows x 36 cols f32 = 36864B (fits A0+A1)
#define DPAD     36

// ---- gemm_x_mma SMEM layout --------------------------------------------------
#define GX_RS    72
#define GX_AHI   0
#define GX_ALO   18432
#define GX_BHI   36864
#define GX_BLO   46080
#define GX_BUF   55296
#define GX_SMEM  110592

// -------- device scratch -----------------------------------------------------
__device__ float g_Whp[(size_t)HID * NG];
__device__ float g_ball[NG];
__device__ float g_Gx[(size_t)M1 * NG];
__device__ unsigned short g_Xhi[(size_t)M1 * DIN];
__device__ unsigned short g_Xlo[(size_t)M1 * DIN];
__device__ unsigned short g_Wxhi[(size_t)NG * DIN];
__device__ unsigned short g_Wxlo[(size_t)NG * DIN];
__device__ unsigned short g_hhi[2][BATCH * HID];   // bf16 hi of h
__device__ char g_h8lo[2][BATCH * HID];            // int8 lo*2^16
__device__ char g_h8hi[2][BATCH * HID];            // int8 hi*2^7
__device__ unsigned g_sync;

// ---- helpers ------------------------------------------------------------
__device__ __forceinline__ unsigned smem_u32(const void* p) {
    unsigned a;
    asm("{ .reg .u64 t; cvta.to.shared.u64 t, %1; cvt.u32.u64 %0, t; }" : "=r"(a) : "l"(p));
    return a;
}
__device__ __forceinline__ void ldsm4(unsigned* r, unsigned addr) {
    asm volatile("ldmatrix.sync.aligned.m8n8.x4.shared.b16 {%0,%1,%2,%3}, [%4];"
        : "=r"(r[0]), "=r"(r[1]), "=r"(r[2]), "=r"(r[3]) : "r"(addr));
}
__device__ __forceinline__ void mma_bf16(float* d, const unsigned* a, const unsigned* b) {
    asm volatile("mma.sync.aligned.m16n8k16.row.col.f32.bf16.bf16.f32 "
        "{%0,%1,%2,%3}, {%4,%5,%6,%7}, {%8,%9}, {%0,%1,%2,%3};"
        : "+f"(d[0]), "+f"(d[1]), "+f"(d[2]), "+f"(d[3])
        : "r"(a[0]), "r"(a[1]), "r"(a[2]), "r"(a[3]), "r"(b[0]), "r"(b[1]));
}
__device__ __forceinline__ void mma_s8(int* d, const unsigned* a, const unsigned* b) {
    asm volatile("mma.sync.aligned.m16n8k32.row.col.s32.s8.s8.s32 "
        "{%0,%1,%2,%3}, {%4,%5,%6,%7}, {%8,%9}, {%0,%1,%2,%3};"
        : "+r"(d[0]), "+r"(d[1]), "+r"(d[2]), "+r"(d[3])
        : "r"(a[0]), "r"(a[1]), "r"(a[2]), "r"(a[3]), "r"(b[0]), "r"(b[1]));
}
__device__ __forceinline__ void cp16(unsigned dst, const void* src) {
    asm volatile("cp.async.cg.shared.global [%0], [%1], 16;" :: "r"(dst), "l"(src));
}
#define CP_COMMIT() asm volatile("cp.async.commit_group;" ::: "memory")
#define CP_WAIT0()  asm volatile("cp.async.wait_group 0;" ::: "memory")

__device__ __forceinline__ void split2(float x, float y, unsigned& hi, unsigned& lo) {
    unsigned h;
    asm("cvt.rn.bf16x2.f32 %0, %1, %2;" : "=r"(h) : "f"(y), "f"(x));
    float hx = __uint_as_float(h << 16);
    float hy = __uint_as_float(h & 0xffff0000u);
    float lx = x - hx, ly = y - hy;
    asm("cvt.rn.bf16x2.f32 %0, %1, %2;" : "=r"(lo) : "f"(ly), "f"(lx));
    hi = h;
}
__device__ __forceinline__ int sat8(float v) {
    int i = __float2int_rn(v);
    return min(127, max(-128, i));
}
// fast activations (MUFU EX2 based)
__device__ __forceinline__ float fsig(float x)  { return 1.0f / (1.0f + __expf(-x)); }
__device__ __forceinline__ float ftanh(float x) { return 1.0f - 2.0f / (1.0f + __expf(2.0f * x)); }

// ---------------------------------------------------------------------------
__global__ void init_kernel(const float* __restrict__ bf, const float* __restrict__ bi,
                            const float* __restrict__ bg, const float* __restrict__ bo) {
    int idx = blockIdx.x * blockDim.x + threadIdx.x;
    if (idx < BATCH * HID) {
        g_hhi[0][idx] = 0; g_hhi[1][idx] = 0;
        g_h8lo[0][idx] = 0; g_h8lo[1][idx] = 0;
        g_h8hi[0][idx] = 0; g_h8hi[1][idx] = 0;
    }
    if (idx < NG) {
        int gate = idx >> 10;
        int j = idx & (HID - 1);
        const float* b = (gate == 0) ? bf : (gate == 1) ? bi : (gate == 2) ? bg : bo;
        g_ball[idx] = b[j];
    }
    if (idx == 0) g_sync = 0u;
}

__global__ void pack_kernel(const float* __restrict__ Wf, const float* __restrict__ Wi,
                            const float* __restrict__ Wg, const float* __restrict__ Wo) {
    __shared__ float tile[32][33];
    int tx = threadIdx.x, ty = threadIdx.y;
    int k0 = DIN + blockIdx.x * 32;
    int n0 = blockIdx.y * 32;
    int gate = n0 >> 10;
    const float* W = (gate == 0) ? Wf : (gate == 1) ? Wi : (gate == 2) ? Wg : Wo;
    int j0 = n0 & (HID - 1);

    tile[ty][tx] = W[(size_t)(j0 + ty) * DH + (k0 + tx)];
    __syncthreads();

    int k = k0 + ty;
    int n = n0 + tx;
    float v = tile[tx][ty];
    int kk = k - DIN;
    int j = n & (HID - 1);
    int g = n >> 10;
    int blk = j >> 3;
    int c = (j & 7) * 4 + g;
    g_Whp[((size_t)blk * CPB + c) * HID + kk] = v;
}

__global__ void wxpack_kernel(const float* __restrict__ Wf, const float* __restrict__ Wi,
                              const float* __restrict__ Wg, const float* __restrict__ Wo) {
    int i4 = blockIdx.x * blockDim.x + threadIdx.x;
    if (i4 >= NG * DIN / 4) return;
    int n = i4 >> 7;
    int k = (i4 & 127) << 2;
    int gate = n >> 10;
    int j = n & (HID - 1);
    const float* W = (gate == 0) ? Wf : (gate == 1) ? Wi : (gate == 2) ? Wg : Wo;
    float4 v = *(const float4*)(W + (size_t)j * DH + k);
    unsigned h01, l01, h23, l23;
    split2(v.x, v.y, h01, l01);
    split2(v.z, v.w, h23, l23);
    *(uint2*)&g_Wxhi[(size_t)n * DIN + k] = make_uint2(h01, h23);
    *(uint2*)&g_Wxlo[(size_t)n * DIN + k] = make_uint2(l01, l23);
}

__global__ void xsplit_kernel(const float* __restrict__ X) {
    int i4 = blockIdx.x * blockDim.x + threadIdx.x;
    if (i4 >= M1 * DIN / 4) return;
    size_t e = (size_t)i4 << 2;
    float4 v = *(const float4*)(X + e);
    unsigned h01, l01, h23, l23;
    split2(v.x, v.y, h01, l01);
    split2(v.z, v.w, h23, l23);
    *(uint2*)&g_Xhi[e] = make_uint2(h01, h23);
    *(uint2*)&g_Xlo[e] = make_uint2(l01, l23);
}

// ---------------------------------------------------------------------------
// gemm_x_mma: Gx = X @ WxT + b, bf16 mma, 3-product split (validated R10)
// ---------------------------------------------------------------------------
__global__ void __launch_bounds__(256) gemm_x_mma(int dummy) {
    extern __shared__ char smem[];
    const unsigned sbase = smem_u32(smem);
    const int tid = threadIdx.x;
    const int w   = tid >> 5;
    const int lid = tid & 31;
    const int n0  = blockIdx.x * 64;
    const int m0  = blockIdx.y * 128;
    const int gate = n0 >> 10;
    const int jb   = n0 & (HID - 1);

    const unsigned a_off = (unsigned)((16 * w + (lid & 15)) * GX_RS + ((lid >> 4) << 3)) * 2;
    const unsigned b_off = (unsigned)((((lid >> 4) << 3) | (lid & 7)) * GX_RS
                                      + (((lid >> 3) & 1) << 3)) * 2;

    float acc[8][4];
    #pragma unroll
    for (int nt = 0; nt < 8; nt++)
        #pragma unroll
        for (int r = 0; r < 4; r++) acc[nt][r] = 0.f;

    const int st_c8 = (tid & 7) << 3;

    {
        const int k0 = 0;
        #pragma unroll
        for (int it = 0; it < 4; it++) {
            int row = (it << 5) + (tid >> 3);
            cp16(sbase + GX_AHI + (unsigned)(row * GX_RS + st_c8) * 2,
                 g_Xhi + (size_t)(m0 + row) * DIN + k0 + st_c8);
            cp16(sbase + GX_ALO + (unsigned)(row * GX_RS + st_c8) * 2,
                 g_Xlo + (size_t)(m0 + row) * DIN + k0 + st_c8);
        }
        #pragma unroll
        for (int it = 0; it < 2; it++) {
            int row = (it << 5) + (tid >> 3);
            cp16(sbase + GX_BHI + (unsigned)(row * GX_RS + st_c8) * 2,
                 g_Wxhi + (size_t)(n0 + row) * DIN + k0 + st_c8);
            cp16(sbase + GX_BLO + (unsigned)(row * GX_RS + st_c8) * 2,
                 g_Wxlo + (size_t)(n0 + row) * DIN + k0 + st_c8);
        }
        CP_COMMIT();
        CP_WAIT0();
        __syncthreads();
    }

    for (int ch = 0; ch < 8; ch++) {
        const unsigned buf = sbase + (ch & 1) * GX_BUF;
        if (ch < 7) {
            const int k0 = (ch + 1) << 6;
            const unsigned dbuf = sbase + ((ch + 1) & 1) * GX_BUF;
            #pragma unroll
            for (int it = 0; it < 4; it++) {
                int row = (it << 5) + (tid >> 3);
                cp16(dbuf + GX_AHI + (unsigned)(row * GX_RS + st_c8) * 2,
                     g_Xhi + (size_t)(m0 + row) * DIN + k0 + st_c8);
                cp16(dbuf + GX_ALO + (unsigned)(row * GX_RS + st_c8) * 2,
                     g_Xlo + (size_t)(m0 + row) * DIN + k0 + st_c8);
            }
            #pragma unroll
            for (int it = 0; it < 2; it++) {
                int row = (it << 5) + (tid >> 3);
                cp16(dbuf + GX_BHI + (unsigned)(row * GX_RS + st_c8) * 2,
                     g_Wxhi + (size_t)(n0 + row) * DIN + k0 + st_c8);
                cp16(dbuf + GX_BLO + (unsigned)(row * GX_RS + st_c8) * 2,
                     g_Wxlo + (size_t)(n0 + row) * DIN + k0 + st_c8);
            }
            CP_COMMIT();
        }

        #pragma unroll
        for (int kk = 0; kk < 4; kk++) {
            const unsigned ko = (unsigned)(kk << 5);
            unsigned ahi[4], alo[4];
            ldsm4(ahi, buf + GX_AHI + a_off + ko);
            ldsm4(alo, buf + GX_ALO + a_off + ko);
            #pragma unroll
            for (int s = 0; s < 4; s++) {
                const unsigned so = (unsigned)(s * 16 * GX_RS * 2);
                unsigned bhi[4], blo[4];
                ldsm4(bhi, buf + GX_BHI + b_off + so + ko);
                ldsm4(blo, buf + GX_BLO + b_off + so + ko);
                mma_bf16(acc[2 * s],     ahi, bhi + 0);
                mma_bf16(acc[2 * s],     alo, bhi + 0);
                mma_bf16(acc[2 * s],     ahi, blo + 0);
                mma_bf16(acc[2 * s + 1], ahi, bhi + 2);
                mma_bf16(acc[2 * s + 1], alo, bhi + 2);
                mma_bf16(acc[2 * s + 1], ahi, blo + 2);
            }
        }

        if (ch < 7) {
            CP_WAIT0();
            __syncthreads();
        }
    }

    const int r0 = m0 + 16 * w + (lid >> 2);
    #pragma unroll
    for (int nt = 0; nt < 8; nt++) {
        int jc = jb + nt * 8 + (lid & 3) * 2;
        float b0 = g_ball[(gate << 10) + jc];
        float b1 = g_ball[(gate << 10) + jc + 1];
        g_Gx[(size_t)r0 * NG + jc * 4 + gate]           = acc[nt][0] + b0;
        g_Gx[(size_t)r0 * NG + (jc + 1) * 4 + gate]     = acc[nt][1] + b1;
        g_Gx[(size_t)(r0 + 8) * NG + jc * 4 + gate]     = acc[nt][2] + b0;
        g_Gx[(size_t)(r0 + 8) * NG + (jc + 1) * 4 + gate] = acc[nt][3] + b1;
    }
}

// ---------------------------------------------------------------------------
// Persistent recurrence: 128 blocks x 512 threads.
//   Main product (hi.Whi, bf16, 1024 mma): warps 0-7 (kh = w>>2 k-half, mt = w&3).
//   Correction (lo.Whi + hi.Wlo, int8 K-stacked, 1024 mma): warps 8-15
//   (part = (w-8)>>2 in {0=lo.Whi, 1=hi.Wlo}, mt = w&3), scale 2^-28.
// ---------------------------------------------------------------------------
__global__ void __launch_bounds__(THR_R, 1) lstm_persistent(float* __restrict__ out,
                                                            int write_tail) {
    extern __shared__ char smem[];
    const unsigned sbase = smem_u32(smem);
    const int tid = threadIdx.x;
    const int w   = tid >> 5;
    const int lid = tid & 31;
    const int blk = blockIdx.x;

    const bool is_main = (w < 8);
    const int mt   = w & 3;
    const int kh   = (w >> 2) & 1;   // main: k-half; corr: part

    // ---- stage weights once: Whi bf16 + corr W int8 (K-stacked) ----
    {
        const float* wsrc = g_Whp + (size_t)blk * CPB * HID;
        for (int i4 = tid; i4 < CPB * HID / 4; i4 += THR_R) {
            int c = i4 >> 8;
            int k = (i4 << 2) & 1023;
            float4 v = *(const float4*)(wsrc + ((size_t)c << 10) + k);
            float vv[4] = {v.x, v.y, v.z, v.w};
            unsigned short hb[4];
            unsigned whi8 = 0, wlo8 = 0;
            #pragma unroll
            for (int e = 0; e < 4; e++) {
                __nv_bfloat16 h = __float2bfloat16(vv[e]);
                hb[e] = *(unsigned short*)&h;
                float hf = __bfloat162float(h);
                float lo = vv[e] - hf;
                whi8 |= ((unsigned)(sat8(hf * 4096.f) & 0xff)) << (8 * e);
                wlo8 |= ((unsigned)(sat8(lo * 2097152.f) & 0xff)) << (8 * e);
            }
            *(uint2*)(smem + SM_WHI + (unsigned)(c * WPAD + k) * 2) =
                make_uint2((unsigned)hb[0] | ((unsigned)hb[1] << 16),
                           (unsigned)hb[2] | ((unsigned)hb[3] << 16));
            *(unsigned*)(smem + SM_W8 + (unsigned)(c * W8PAD + k)) = whi8;
            *(unsigned*)(smem + SM_W8 + (unsigned)(c * W8PAD + 1024 + k)) = wlo8;
        }
    }
    __syncthreads();

    // ldmatrix lane addressing (byte offsets)
    const unsigned a_row  = (unsigned)((16 * mt + (lid & 15)) * A8PAD) + ((lid >> 4) << 4);
    const int c_i   = ((lid >> 4) << 3) + (lid & 7);
    const unsigned khalfB = ((lid >> 3) & 1) << 4;   // 16-byte half
    const unsigned bhi0 = sbase + SM_WHI + (unsigned)(c_i * WPAD) * 2 + khalfB;
    const unsigned bhi1 = bhi0 + 16u * WPAD * 2u;
    const unsigned b8_0 = sbase + SM_W8 + (unsigned)(c_i * W8PAD) + khalfB;
    const unsigned b8_1 = b8_0 + 16u * W8PAD;

    float c_state = 0.f;
    const int b_epi = tid >> 3;
    const int q_epi = tid & 7;
    const long long OUT_MAIN = (long long)T_STEPS * BATCH * HID;

    const size_t gxstep = (size_t)BATCH * NG;
    size_t gxoff = (size_t)b_epi * NG + blk * CPB + 4 * q_epi;
    float4 gxv = *(const float4*)&g_Gx[gxoff];

    // staging decode constants
    const int strowA = tid >> 4;          // A_hi rows (+32 for it1)
    const int stc8A  = (tid & 15) << 3;   // elems
    const int strow8 = tid >> 3;          // int8 rows (it2/it3: tid<512 covers 64 rows)
    const unsigned stsg8 = (tid & 7) << 4; // byte segment

    for (int t = 0; t < T_STEPS; t++) {
        const unsigned short* hhi = g_hhi[t & 1];
        const char* h8lo = g_h8lo[t & 1];
        const char* h8hi = g_h8hi[t & 1];

        // ---- stage chunk 0 ----
        {
            const int k0 = 0;
            cp16(sbase + SM_A0 + (unsigned)(strowA * A8PAD) + (unsigned)(stc8A << 1),
                 hhi + (size_t)strowA * HID + k0 + stc8A);
            cp16(sbase + SM_A0 + (unsigned)((strowA + 32) * A8PAD) + (unsigned)(stc8A << 1),
                 hhi + (size_t)(strowA + 32) * HID + k0 + stc8A);
            cp16(sbase + SM_A0 + A8OFF + (unsigned)(strow8 * A8PAD) + stsg8,
                 h8lo + (size_t)strow8 * HID + k0 + (tid & 7) * 16);
            cp16(sbase + SM_A0 + A8OFF + (unsigned)(strow8 * A8PAD) + 128u + stsg8,
                 h8hi + (size_t)strow8 * HID + k0 + (tid & 7) * 16);
            CP_COMMIT();
            CP_WAIT0();
            __syncthreads();
        }

        float accf[4][4];
        int acci[4][4];
        #pragma unroll
        for (int n = 0; n < 4; n++)
            #pragma unroll
            for (int r = 0; r < 4; r++) { accf[n][r] = 0.f; acci[n][r] = 0; }

        for (int ch = 0; ch < 8; ch++) {
            const unsigned abuf = sbase + ((ch & 1) ? SM_A1 : SM_A0);
            if (ch < 7) {
                const int k0n = (ch + 1) << 7;
                const unsigned dbase = sbase + (((ch + 1) & 1) ? SM_A1 : SM_A0);
                cp16(dbase + (unsigned)(strowA * A8PAD) + (unsigned)(stc8A << 1),
                     hhi + (size_t)strowA * HID + k0n + stc8A);
                cp16(dbase + (unsigned)((strowA + 32) * A8PAD) + (unsigned)(stc8A << 1),
                     hhi + (size_t)(strowA + 32) * HID + k0n + stc8A);
                cp16(dbase + A8OFF + (unsigned)(strow8 * A8PAD) + stsg8,
                     h8lo + (size_t)strow8 * HID + k0n + (tid & 7) * 16);
                cp16(dbase + A8OFF + (unsigned)(strow8 * A8PAD) + 128u + stsg8,
                     h8hi + (size_t)strow8 * HID + k0n + (tid & 7) * 16);
                CP_COMMIT();
            }

            if (is_main) {
                #pragma unroll
                for (int kkl = 0; kkl < 4; kkl++) {
                    const int kk = kh * 4 + kkl;
                    const unsigned akoff = (unsigned)(kk << 5);           // 32B per k16
                    const unsigned wkoff = (unsigned)(((ch << 7) + (kk << 4)) << 1);
                    unsigned a[4], b0[4], b1[4];
                    ldsm4(a, abuf + a_row + akoff);
                    ldsm4(b0, bhi0 + wkoff);
                    ldsm4(b1, bhi1 + wkoff);
                    mma_bf16(accf[0], a, b0 + 0);
                    mma_bf16(accf[1], a, b0 + 2);
                    mma_bf16(accf[2], a, b1 + 0);
                    mma_bf16(accf[3], a, b1 + 2);
                }
            } else {
                #pragma unroll
                for (int kcl = 0; kcl < 4; kcl++) {
                    const unsigned a8off = (unsigned)(kh * 128 + kcl * 32);
                    const unsigned b8off = (unsigned)(kh * 1024 + ch * 128 + kcl * 32);
                    unsigned a[4], b0[4], b1[4];
                    ldsm4(a, abuf + A8OFF + a_row + a8off);
                    ldsm4(b0, b8_0 + b8off);
                    ldsm4(b1, b8_1 + b8off);
                    mma_s8(acci[0], a, b0 + 0);
                    mma_s8(acci[1], a, b0 + 2);
                    mma_s8(acci[2], a, b1 + 0);
                    mma_s8(acci[3], a, b1 + 2);
                }
            }

            if (ch < 7) {
                CP_WAIT0();
                __syncthreads();
            }
        }

        // ---- exchange: all 16 warps write disjoint D rows ----
        __syncthreads();
        {
            float* D = (float*)(smem + SM_D);
            const int rr = lid >> 2;
            const int cc = 2 * (lid & 3);
            if (is_main) {
                int r0 = (kh << 6) + 16 * mt + rr;           // rows 0..127
                #pragma unroll
                for (int nt = 0; nt < 4; nt++) {
                    int col = 8 * nt + cc;
                    *(float2*)&D[r0 * DPAD + col]       = make_float2(accf[nt][0], accf[nt][1]);
                    *(float2*)&D[(r0 + 8) * DPAD + col] = make_float2(accf[nt][2], accf[nt][3]);
                }
            } else {
                const float s = 1.f / 268435456.f;           // 2^-28
                int r0 = 128 + (kh << 6) + 16 * mt + rr;     // rows 128..255
                #pragma unroll
                for (int nt = 0; nt < 4; nt++) {
                    int col = 8 * nt + cc;
                    *(float2*)&D[r0 * DPAD + col] =
                        make_float2((float)acci[nt][0] * s, (float)acci[nt][1] * s);
                    *(float2*)&D[(r0 + 8) * DPAD + col] =
                        make_float2((float)acci[nt][2] * s, (float)acci[nt][3] * s);
                }
            }
        }
        __syncthreads();

        // ---- fused epilogue: thread owns (b, 1 j-unit) ----
        float hout, cout;
        {
            const float* D = (const float*)(smem + SM_D);
            const int b = b_epi;
            const int c0 = 4 * q_epi;
            float4 d0 = *(const float4*)&D[b * DPAD + c0];
            float4 d1 = *(const float4*)&D[(64 + b) * DPAD + c0];
            float4 d2 = *(const float4*)&D[(128 + b) * DPAD + c0];
            float4 d3 = *(const float4*)&D[(192 + b) * DPAD + c0];
            float pf = d0.x + d1.x + d2.x + d3.x + gxv.x;
            float pi = d0.y + d1.y + d2.y + d3.y + gxv.y;
            float pg = d0.z + d1.z + d2.z + d3.z + gxv.z;
            float po = d0.w + d1.w + d2.w + d3.w + gxv.w;
            float f = fsig(pf);
            float i = fsig(pi);
            float g = ftanh(pg);
            float o = fsig(po);
            cout = f * c_state + i * g;
            hout = o * ftanh(cout);
            c_state = cout;
        }
        __nv_bfloat16 hb = __float2bfloat16(hout);
        float hf = __bfloat162float(hb);
        const int jg = blk * JPB + q_epi;
        const int hoff = b_epi * HID + jg;
        g_hhi[(t + 1) & 1][hoff] = *(unsigned short*)&hb;
        g_h8lo[(t + 1) & 1][hoff] = (char)sat8((hout - hf) * 65536.f);
        g_h8hi[(t + 1) & 1][hoff] = (char)sat8(hf * 128.f);

        // ---- out stores (off the sync critical path) ----
        out[(size_t)t * (BATCH * HID) + hoff] = hout;
        if (t == T_STEPS - 1) {
            if (write_tail) {
                out[OUT_MAIN + hoff] = hout;
                out[OUT_MAIN + BATCH * HID + hoff] = cout;
            }
            break;
        }

        // ---- grid barrier (single atomic counter, best measured) ----
        __threadfence();
        __syncthreads();
        if (tid == 0) atomicAdd(&g_sync, 1u);

        {
            size_t go = gxoff + (size_t)(t + 1) * gxstep;
            gxv = *(const float4*)&g_Gx[go];
        }

        if (tid == 0) {
            unsigned target = (unsigned)GRID_P * (unsigned)(t + 1);
            while (*(volatile unsigned*)&g_sync < target) { }
            __threadfence();
        }
        __syncthreads();
    }
}

// ---------------------------------------------------------------------------
extern "C" void kernel_launch(void* const* d_in, const int* in_sizes, int n_in,
                              void* d_out, int out_size) {
    const float* X  = (const float*)d_in[0];
    const float* Wf = (const float*)d_in[1];
    const float* bf = (const float*)d_in[2];
    const float* Wi = (const float*)d_in[3];
    const float* bi = (const float*)d_in[4];
    const float* Wg = (const float*)d_in[5];
    const float* bg = (const float*)d_in[6];
    const float* Wo = (const float*)d_in[7];
    const float* bo = (const float*)d_in[8];
    float* out = (float*)d_out;

    cudaFuncSetAttribute(lstm_persistent,
                         cudaFuncAttributeMaxDynamicSharedMemorySize, SMEM_TOTAL);
    cudaFuncSetAttribute(gemm_x_mma,
                         cudaFuncAttributeMaxDynamicSharedMemorySize, GX_SMEM);

    init_kernel<<<(BATCH * HID + 255) / 256, 256>>>(bf, bi, bg, bo);
    pack_kernel<<<dim3((DH - DIN) / 32, NG / 32), dim3(32, 32)>>>(Wf, Wi, Wg, Wo);
    wxpack_kernel<<<(NG * DIN / 4 + 255) / 256, 256>>>(Wf, Wi, Wg, Wo);
    xsplit_kernel<<<(M1 * DIN / 4 + 255) / 256, 256>>>(X);
    gemm_x_mma<<<dim3(NG / 64, M1 / 128), 256, GX_SMEM>>>(0);

    const long long OUT_MAIN = (long long)T_STEPS * BATCH * HID;
    int write_tail = ((long long)out_size >= OUT_MAIN + 2LL * BATCH * HID) ? 1 : 0;

    lstm_persistent<<<GRID_P, THR_R, SMEM_TOTAL>>>(out, write_tail);
}

// round 14
// speedup vs baseline: 1.4989x; 1.4989x over previous
#include <cuda_runtime.h>
#include <cuda_bf16.h>
#include <math.h>

// Problem constants
#define T_STEPS 256
#define BATCH   64
#define DIN     512
#define HID     1024
#define DH      (DIN + HID)       // 1536
#define NG      (4 * HID)         // 4096
#define M1      (T_STEPS * BATCH) // 16384

#define GRID_P  128               // persistent blocks
#define THR_R   512               // 16 warps (recurrence)
#define JPB     8                 // j-units per block
#define CPB     32                // gate-columns per block

// ---- LSTM SMEM layout (bytes) ------------------------------------------------
#define WPAD     1032
#define SM_WHI   0
#define SM_WLO   66048
// A ring: 4 buffers of [128 rows][72 elems] bf16 = 18432 B each
#define APAD2    72
#define ABUF2    18432
#define SM_AB    132096
#define SMEM_TOTAL (SM_AB + 4 * ABUF2)   // 205824
#define SM_D     SM_AB                    // D: 384x36 f32 = 55296 <= 73728 ring
#define DPAD     36

// ---- gemm_x_mma SMEM layout --------------------------------------------------
#define GX_RS    72
#define GX_AHI   0
#define GX_ALO   18432
#define GX_BHI   36864
#define GX_BLO   46080
#define GX_BUF   55296
#define GX_SMEM  110592

// -------- device scratch -----------------------------------------------------
__device__ float g_Whp[(size_t)HID * NG];
__device__ float g_ball[NG];
__device__ float g_Gx[(size_t)M1 * NG];
__device__ unsigned short g_Xhi[(size_t)M1 * DIN];
__device__ unsigned short g_Xlo[(size_t)M1 * DIN];
__device__ unsigned short g_Wxhi[(size_t)NG * DIN];
__device__ unsigned short g_Wxlo[(size_t)NG * DIN];
__device__ unsigned short g_hhi[2][BATCH * HID];
__device__ unsigned short g_hlo[2][BATCH * HID];
__device__ unsigned g_sync;

// ---- helpers ------------------------------------------------------------
__device__ __forceinline__ unsigned smem_u32(const void* p) {
    unsigned a;
    asm("{ .reg .u64 t; cvta.to.shared.u64 t, %1; cvt.u32.u64 %0, t; }" : "=r"(a) : "l"(p));
    return a;
}
__device__ __forceinline__ void ldsm4(unsigned* r, unsigned addr) {
    asm volatile("ldmatrix.sync.aligned.m8n8.x4.shared.b16 {%0,%1,%2,%3}, [%4];"
        : "=r"(r[0]), "=r"(r[1]), "=r"(r[2]), "=r"(r[3]) : "r"(addr));
}
__device__ __forceinline__ void mma_bf16(float* d, const unsigned* a, const unsigned* b) {
    asm volatile("mma.sync.aligned.m16n8k16.row.col.f32.bf16.bf16.f32 "
        "{%0,%1,%2,%3}, {%4,%5,%6,%7}, {%8,%9}, {%0,%1,%2,%3};"
        : "+f"(d[0]), "+f"(d[1]), "+f"(d[2]), "+f"(d[3])
        : "r"(a[0]), "r"(a[1]), "r"(a[2]), "r"(a[3]), "r"(b[0]), "r"(b[1]));
}
__device__ __forceinline__ void cp16(unsigned dst, const void* src) {
    asm volatile("cp.async.cg.shared.global [%0], [%1], 16;" :: "r"(dst), "l"(src));
}
#define CP_COMMIT() asm volatile("cp.async.commit_group;" ::: "memory")
#define CP_WAIT0()  asm volatile("cp.async.wait_group 0;" ::: "memory")
#define CP_WAIT1()  asm volatile("cp.async.wait_group 1;" ::: "memory")
#define CP_WAIT2()  asm volatile("cp.async.wait_group 2;" ::: "memory")

__device__ __forceinline__ void split2(float x, float y, unsigned& hi, unsigned& lo) {
    unsigned h;
    asm("cvt.rn.bf16x2.f32 %0, %1, %2;" : "=r"(h) : "f"(y), "f"(x));
    float hx = __uint_as_float(h << 16);
    float hy = __uint_as_float(h & 0xffff0000u);
    float lx = x - hx, ly = y - hy;
    asm("cvt.rn.bf16x2.f32 %0, %1, %2;" : "=r"(lo) : "f"(ly), "f"(lx));
    hi = h;
}
// fast activations (MUFU EX2 based)
__device__ __forceinline__ float fsig(float x)  { return 1.0f / (1.0f + __expf(-x)); }
__device__ __forceinline__ float ftanh(float x) { return 1.0f - 2.0f / (1.0f + __expf(2.0f * x)); }

// ---------------------------------------------------------------------------
__global__ void init_kernel(const float* __restrict__ bf, const float* __restrict__ bi,
                            const float* __restrict__ bg, const float* __restrict__ bo) {
    int idx = blockIdx.x * blockDim.x + threadIdx.x;
    if (idx < BATCH * HID) {
        g_hhi[0][idx] = 0; g_hhi[1][idx] = 0;
        g_hlo[0][idx] = 0; g_hlo[1][idx] = 0;
    }
    if (idx < NG) {
        int gate = idx >> 10;
        int j = idx & (HID - 1);
        const float* b = (gate == 0) ? bf : (gate == 1) ? bi : (gate == 2) ? bg : bo;
        g_ball[idx] = b[j];
    }
    if (idx == 0) g_sync = 0u;
}

__global__ void pack_kernel(const float* __restrict__ Wf, const float* __restrict__ Wi,
                            const float* __restrict__ Wg, const float* __restrict__ Wo) {
    __shared__ float tile[32][33];
    int tx = threadIdx.x, ty = threadIdx.y;
    int k0 = DIN + blockIdx.x * 32;
    int n0 = blockIdx.y * 32;
    int gate = n0 >> 10;
    const float* W = (gate == 0) ? Wf : (gate == 1) ? Wi : (gate == 2) ? Wg : Wo;
    int j0 = n0 & (HID - 1);

    tile[ty][tx] = W[(size_t)(j0 + ty) * DH + (k0 + tx)];
    __syncthreads();

    int k = k0 + ty;
    int n = n0 + tx;
    float v = tile[tx][ty];
    int kk = k - DIN;
    int j = n & (HID - 1);
    int g = n >> 10;
    int blk = j >> 3;
    int c = (j & 7) * 4 + g;
    g_Whp[((size_t)blk * CPB + c) * HID + kk] = v;
}

__global__ void wxpack_kernel(const float* __restrict__ Wf, const float* __restrict__ Wi,
                              const float* __restrict__ Wg, const float* __restrict__ Wo) {
    int i4 = blockIdx.x * blockDim.x + threadIdx.x;
    if (i4 >= NG * DIN / 4) return;
    int n = i4 >> 7;
    int k = (i4 & 127) << 2;
    int gate = n >> 10;
    int j = n & (HID - 1);
    const float* W = (gate == 0) ? Wf : (gate == 1) ? Wi : (gate == 2) ? Wg : Wo;
    float4 v = *(const float4*)(W + (size_t)j * DH + k);
    unsigned h01, l01, h23, l23;
    split2(v.x, v.y, h01, l01);
    split2(v.z, v.w, h23, l23);
    *(uint2*)&g_Wxhi[(size_t)n * DIN + k] = make_uint2(h01, h23);
    *(uint2*)&g_Wxlo[(size_t)n * DIN + k] = make_uint2(l01, l23);
}

__global__ void xsplit_kernel(const float* __restrict__ X) {
    int i4 = blockIdx.x * blockDim.x + threadIdx.x;
    if (i4 >= M1 * DIN / 4) return;
    size_t e = (size_t)i4 << 2;
    float4 v = *(const float4*)(X + e);
    unsigned h01, l01, h23, l23;
    split2(v.x, v.y, h01, l01);
    split2(v.z, v.w, h23, l23);
    *(uint2*)&g_Xhi[e] = make_uint2(h01, h23);
    *(uint2*)&g_Xlo[e] = make_uint2(l01, l23);
}

// ---------------------------------------------------------------------------
// gemm_x_mma: Gx = X @ WxT + b, bf16 mma, 3-product split (validated R10)
// ---------------------------------------------------------------------------
__global__ void __launch_bounds__(256) gemm_x_mma(int dummy) {
    extern __shared__ char smem[];
    const unsigned sbase = smem_u32(smem);
    const int tid = threadIdx.x;
    const int w   = tid >> 5;
    const int lid = tid & 31;
    const int n0  = blockIdx.x * 64;
    const int m0  = blockIdx.y * 128;
    const int gate = n0 >> 10;
    const int jb   = n0 & (HID - 1);

    const unsigned a_off = (unsigned)((16 * w + (lid & 15)) * GX_RS + ((lid >> 4) << 3)) * 2;
    const unsigned b_off = (unsigned)((((lid >> 4) << 3) | (lid & 7)) * GX_RS
                                      + (((lid >> 3) & 1) << 3)) * 2;

    float acc[8][4];
    #pragma unroll
    for (int nt = 0; nt < 8; nt++)
        #pragma unroll
        for (int r = 0; r < 4; r++) acc[nt][r] = 0.f;

    const int st_c8 = (tid & 7) << 3;

    {
        const int k0 = 0;
        #pragma unroll
        for (int it = 0; it < 4; it++) {
            int row = (it << 5) + (tid >> 3);
            cp16(sbase + GX_AHI + (unsigned)(row * GX_RS + st_c8) * 2,
                 g_Xhi + (size_t)(m0 + row) * DIN + k0 + st_c8);
            cp16(sbase + GX_ALO + (unsigned)(row * GX_RS + st_c8) * 2,
                 g_Xlo + (size_t)(m0 + row) * DIN + k0 + st_c8);
        }
        #pragma unroll
        for (int it = 0; it < 2; it++) {
            int row = (it << 5) + (tid >> 3);
            cp16(sbase + GX_BHI + (unsigned)(row * GX_RS + st_c8) * 2,
                 g_Wxhi + (size_t)(n0 + row) * DIN + k0 + st_c8);
            cp16(sbase + GX_BLO + (unsigned)(row * GX_RS + st_c8) * 2,
                 g_Wxlo + (size_t)(n0 + row) * DIN + k0 + st_c8);
        }
        CP_COMMIT();
        CP_WAIT0();
        __syncthreads();
    }

    for (int ch = 0; ch < 8; ch++) {
        const unsigned buf = sbase + (ch & 1) * GX_BUF;
        if (ch < 7) {
            const int k0 = (ch + 1) << 6;
            const unsigned dbuf = sbase + ((ch + 1) & 1) * GX_BUF;
            #pragma unroll
            for (int it = 0; it < 4; it++) {
                int row = (it << 5) + (tid >> 3);
                cp16(dbuf + GX_AHI + (unsigned)(row * GX_RS + st_c8) * 2,
                     g_Xhi + (size_t)(m0 + row) * DIN + k0 + st_c8);
                cp16(dbuf + GX_ALO + (unsigned)(row * GX_RS + st_c8) * 2,
                     g_Xlo + (size_t)(m0 + row) * DIN + k0 + st_c8);
            }
            #pragma unroll
            for (int it = 0; it < 2; it++) {
                int row = (it << 5) + (tid >> 3);
                cp16(dbuf + GX_BHI + (unsigned)(row * GX_RS + st_c8) * 2,
                     g_Wxhi + (size_t)(n0 + row) * DIN + k0 + st_c8);
                cp16(dbuf + GX_BLO + (unsigned)(row * GX_RS + st_c8) * 2,
                     g_Wxlo + (size_t)(n0 + row) * DIN + k0 + st_c8);
            }
            CP_COMMIT();
        }

        #pragma unroll
        for (int kk = 0; kk < 4; kk++) {
            const unsigned ko = (unsigned)(kk << 5);
            unsigned ahi[4], alo[4];
            ldsm4(ahi, buf + GX_AHI + a_off + ko);
            ldsm4(alo, buf + GX_ALO + a_off + ko);
            #pragma unroll
            for (int s = 0; s < 4; s++) {
                const unsigned so = (unsigned)(s * 16 * GX_RS * 2);
                unsigned bhi[4], blo[4];
                ldsm4(bhi, buf + GX_BHI + b_off + so + ko);
                ldsm4(blo, buf + GX_BLO + b_off + so + ko);
                mma_bf16(acc[2 * s],     ahi, bhi + 0);
                mma_bf16(acc[2 * s],     alo, bhi + 0);
                mma_bf16(acc[2 * s],     ahi, blo + 0);
                mma_bf16(acc[2 * s + 1], ahi, bhi + 2);
                mma_bf16(acc[2 * s + 1], alo, bhi + 2);
                mma_bf16(acc[2 * s + 1], ahi, blo + 2);
            }
        }

        if (ch < 7) {
            CP_WAIT0();
            __syncthreads();
        }
    }

    const int r0 = m0 + 16 * w + (lid >> 2);
    #pragma unroll
    for (int nt = 0; nt < 8; nt++) {
        int jc = jb + nt * 8 + (lid & 3) * 2;
        float b0 = g_ball[(gate << 10) + jc];
        float b1 = g_ball[(gate << 10) + jc + 1];
        g_Gx[(size_t)r0 * NG + jc * 4 + gate]           = acc[nt][0] + b0;
        g_Gx[(size_t)r0 * NG + (jc + 1) * 4 + gate]     = acc[nt][1] + b1;
        g_Gx[(size_t)(r0 + 8) * NG + jc * 4 + gate]     = acc[nt][2] + b0;
        g_Gx[(size_t)(r0 + 8) * NG + (jc + 1) * 4 + gate] = acc[nt][3] + b1;
    }
}

// ---------------------------------------------------------------------------
// Persistent recurrence (R12 engine) with a 4-deep cp.async pipeline:
//   16 K-chunks of 64; prefetch depth 3 (wait_group 2) hides L2 latency.
//   Warp kh = w>>2 (k-quarter) computes kk = kh within each chunk.
//   Exchange/epilogue/barrier identical to R12.
// ---------------------------------------------------------------------------
__global__ void __launch_bounds__(THR_R, 1) lstm_persistent(float* __restrict__ out,
                                                            int write_tail) {
    extern __shared__ char smem[];
    const unsigned sbase = smem_u32(smem);
    const int tid = threadIdx.x;
    const int w   = tid >> 5;
    const int lid = tid & 31;
    const int kh  = w >> 2;            // 0..3: which k16 of each 64-chunk
    const int wl  = w & 3;
    const int blk = blockIdx.x;

    // ---- stage weights once ----
    {
        const float* wsrc = g_Whp + (size_t)blk * CPB * HID;
        for (int i4 = tid; i4 < CPB * HID / 4; i4 += THR_R) {
            int c = i4 >> 8;
            int k = (i4 << 2) & 1023;
            float4 v = *(const float4*)(wsrc + ((size_t)c << 10) + k);
            unsigned h01, l01, h23, l23;
            split2(v.x, v.y, h01, l01);
            split2(v.z, v.w, h23, l23);
            unsigned off = (unsigned)(c * WPAD + k) * 2;
            *(uint2*)(smem + SM_WHI + off) = make_uint2(h01, h23);
            *(uint2*)(smem + SM_WLO + off) = make_uint2(l01, l23);
        }
    }
    __syncthreads();

    const unsigned a0_row = (unsigned)((16 * wl + (lid & 15)) * APAD2 + ((lid >> 4) << 3)) * 2;
    const unsigned A1OFF  = 64u * APAD2 * 2u;
    const int c_i   = ((lid >> 4) << 3) + (lid & 7);
    const int khalf = ((lid >> 3) & 1) << 3;
    const unsigned bhi0 = sbase + SM_WHI + (unsigned)(c_i * WPAD + khalf) * 2;
    const unsigned bhi1 = sbase + SM_WHI + (unsigned)((16 + c_i) * WPAD + khalf) * 2;
    const unsigned blo0 = sbase + SM_WLO + (unsigned)(c_i * WPAD + khalf) * 2;
    const unsigned blo1 = sbase + SM_WLO + (unsigned)((16 + c_i) * WPAD + khalf) * 2;

    float c_state = 0.f;
    const int b_epi = tid >> 3;
    const int q_epi = tid & 7;
    const long long OUT_MAIN = (long long)T_STEPS * BATCH * HID;

    const size_t gxstep = (size_t)BATCH * NG;
    size_t gxoff = (size_t)b_epi * NG + blk * CPB + 4 * q_epi;
    float4 gxv = *(const float4*)&g_Gx[gxoff];

    // staging decode (2 cp16/thread/chunk): slot = it*512+tid -> row, c8
    const int st_row0 = tid >> 3;             // slot0 row (0..63)
    const int st_row1 = (tid >> 3) + 64;      // slot1 row (64..127)
    const int st_c8   = (tid & 7) << 3;

    for (int t = 0; t < T_STEPS; t++) {
        const unsigned short* hhi = g_hhi[t & 1];
        const unsigned short* hlo = g_hlo[t & 1];

        // ---- prologue: stage chunks 0,1,2 ----
        #pragma unroll
        for (int p = 0; p < 3; p++) {
            const int k0s = p << 6;
            const unsigned bufb = sbase + SM_AB + (unsigned)(p * ABUF2);
            cp16(bufb + (unsigned)(st_row0 * APAD2 + st_c8) * 2,
                 hhi + (size_t)st_row0 * HID + k0s + st_c8);
            cp16(bufb + (unsigned)(st_row1 * APAD2 + st_c8) * 2,
                 hlo + (size_t)(st_row1 - 64) * HID + k0s + st_c8);
            CP_COMMIT();
        }

        float acc1[2][4][4], acc2[4][4];
        #pragma unroll
        for (int tl = 0; tl < 2; tl++)
            #pragma unroll
            for (int n = 0; n < 4; n++)
                #pragma unroll
                for (int r = 0; r < 4; r++) acc1[tl][n][r] = 0.f;
        #pragma unroll
        for (int n = 0; n < 4; n++)
            #pragma unroll
            for (int r = 0; r < 4; r++) acc2[n][r] = 0.f;

        for (int ch = 0; ch < 16; ch++) {
            // wait for chunk ch's group (depth-aware)
            if (ch < 14)      { CP_WAIT2(); }
            else if (ch == 14){ CP_WAIT1(); }
            else              { CP_WAIT0(); }
            __syncthreads();

            // prefetch chunk ch+3
            if (ch + 3 < 16) {
                const int k0s = (ch + 3) << 6;
                const unsigned bufb = sbase + SM_AB + (unsigned)(((ch + 3) & 3) * ABUF2);
                cp16(bufb + (unsigned)(st_row0 * APAD2 + st_c8) * 2,
                     hhi + (size_t)st_row0 * HID + k0s + st_c8);
                cp16(bufb + (unsigned)(st_row1 * APAD2 + st_c8) * 2,
                     hlo + (size_t)(st_row1 - 64) * HID + k0s + st_c8);
                CP_COMMIT();
            }

            // compute: this warp's k16 (kk = kh) of chunk ch
            {
                const unsigned abuf = sbase + SM_AB + (unsigned)((ch & 3) * ABUF2);
                const unsigned akoff = (unsigned)(kh << 5);
                const unsigned wkoff = (unsigned)(((ch << 6) + (kh << 4)) << 1);
                unsigned a0[4], a1[4], bh0[4], bh1[4], bl0[4], bl1[4];
                ldsm4(a0, abuf + a0_row + akoff);
                ldsm4(bh0, bhi0 + wkoff);
                ldsm4(bh1, bhi1 + wkoff);
                ldsm4(a1, abuf + a0_row + A1OFF + akoff);
                ldsm4(bl0, blo0 + wkoff);
                ldsm4(bl1, blo1 + wkoff);
                mma_bf16(acc1[0][0], a0, bh0 + 0);
                mma_bf16(acc1[0][1], a0, bh0 + 2);
                mma_bf16(acc1[0][2], a0, bh1 + 0);
                mma_bf16(acc1[0][3], a0, bh1 + 2);
                mma_bf16(acc1[1][0], a1, bh0 + 0);
                mma_bf16(acc1[1][1], a1, bh0 + 2);
                mma_bf16(acc1[1][2], a1, bh1 + 0);
                mma_bf16(acc1[1][3], a1, bh1 + 2);
                mma_bf16(acc2[0], a0, bl0 + 0);
                mma_bf16(acc2[1], a0, bl0 + 2);
                mma_bf16(acc2[2], a0, bl1 + 0);
                mma_bf16(acc2[3], a0, bl1 + 2);
            }
        }

        // ---- exchange: pass 1 (kh 0,1 write), pass 2 (kh 2,3 add) ----
        __syncthreads();
        {
            float* D = (float*)(smem + SM_D);
            const int khh = kh & 1;
            const int rr = lid >> 2;
            const int cc = 2 * (lid & 3);
            const int r_t0 = (khh << 7) + 16 * wl + rr;
            const int r_t1 = (khh << 7) + 64 + 16 * wl + rr;
            const int r_a2 = 256 + (khh << 6) + 16 * wl + rr;
            if (kh < 2) {
                #pragma unroll
                for (int nt = 0; nt < 4; nt++) {
                    int col = 8 * nt + cc;
                    *(float2*)&D[r_t0 * DPAD + col]       = make_float2(acc1[0][nt][0], acc1[0][nt][1]);
                    *(float2*)&D[(r_t0 + 8) * DPAD + col] = make_float2(acc1[0][nt][2], acc1[0][nt][3]);
                    *(float2*)&D[r_t1 * DPAD + col]       = make_float2(acc1[1][nt][0], acc1[1][nt][1]);
                    *(float2*)&D[(r_t1 + 8) * DPAD + col] = make_float2(acc1[1][nt][2], acc1[1][nt][3]);
                    *(float2*)&D[r_a2 * DPAD + col]       = make_float2(acc2[nt][0], acc2[nt][1]);
                    *(float2*)&D[(r_a2 + 8) * DPAD + col] = make_float2(acc2[nt][2], acc2[nt][3]);
                }
            }
            __syncthreads();
            if (kh >= 2) {
                #pragma unroll
                for (int nt = 0; nt < 4; nt++) {
                    int col = 8 * nt + cc;
                    float2 v;
                    v = *(float2*)&D[r_t0 * DPAD + col];
                    v.x += acc1[0][nt][0]; v.y += acc1[0][nt][1];
                    *(float2*)&D[r_t0 * DPAD + col] = v;
                    v = *(float2*)&D[(r_t0 + 8) * DPAD + col];
                    v.x += acc1[0][nt][2]; v.y += acc1[0][nt][3];
                    *(float2*)&D[(r_t0 + 8) * DPAD + col] = v;
                    v = *(float2*)&D[r_t1 * DPAD + col];
                    v.x += acc1[1][nt][0]; v.y += acc1[1][nt][1];
                    *(float2*)&D[r_t1 * DPAD + col] = v;
                    v = *(float2*)&D[(r_t1 + 8) * DPAD + col];
                    v.x += acc1[1][nt][2]; v.y += acc1[1][nt][3];
                    *(float2*)&D[(r_t1 + 8) * DPAD + col] = v;
                    v = *(float2*)&D[r_a2 * DPAD + col];
                    v.x += acc2[nt][0]; v.y += acc2[nt][1];
                    *(float2*)&D[r_a2 * DPAD + col] = v;
                    v = *(float2*)&D[(r_a2 + 8) * DPAD + col];
                    v.x += acc2[nt][2]; v.y += acc2[nt][3];
                    *(float2*)&D[(r_a2 + 8) * DPAD + col] = v;
                }
            }
        }
        __syncthreads();

        // ---- fused epilogue: thread owns (b, 1 j-unit) ----
        float hout, cout;
        {
            const float* D = (const float*)(smem + SM_D);
            const int b = b_epi;
            const int c0 = 4 * q_epi;
            float4 d0 = *(const float4*)&D[b * DPAD + c0];
            float4 d1 = *(const float4*)&D[(128 + b) * DPAD + c0];
            float4 d2 = *(const float4*)&D[(64 + b) * DPAD + c0];
            float4 d3 = *(const float4*)&D[(192 + b) * DPAD + c0];
            float4 d4 = *(const float4*)&D[(256 + b) * DPAD + c0];
            float4 d5 = *(const float4*)&D[(320 + b) * DPAD + c0];
            float pf = d0.x + d1.x + d2.x + d3.x + d4.x + d5.x + gxv.x;
            float pi = d0.y + d1.y + d2.y + d3.y + d4.y + d5.y + gxv.y;
            float pg = d0.z + d1.z + d2.z + d3.z + d4.z + d5.z + gxv.z;
            float po = d0.w + d1.w + d2.w + d3.w + d4.w + d5.w + gxv.w;
            float f = fsig(pf);
            float i = fsig(pi);
            float g = ftanh(pg);
            float o = fsig(po);
            cout = f * c_state + i * g;
            hout = o * ftanh(cout);
            c_state = cout;
        }
        __nv_bfloat16 hb = __float2bfloat16(hout);
        float hf = __bfloat162float(hb);
        __nv_bfloat16 lb = __float2bfloat16(hout - hf);
        const int jg = blk * JPB + q_epi;
        const int hoff = b_epi * HID + jg;
        g_hhi[(t + 1) & 1][hoff] = *(unsigned short*)&hb;
        g_hlo[(t + 1) & 1][hoff] = *(unsigned short*)&lb;

        // ---- out stores (off the sync critical path) ----
        out[(size_t)t * (BATCH * HID) + hoff] = hout;
        if (t == T_STEPS - 1) {
            if (write_tail) {
                out[OUT_MAIN + hoff] = hout;
                out[OUT_MAIN + BATCH * HID + hoff] = cout;
            }
            break;
        }

        // ---- grid barrier (single atomic counter) ----
        __threadfence();
        __syncthreads();
        if (tid == 0) atomicAdd(&g_sync, 1u);

        {
            size_t go = gxoff + (size_t)(t + 1) * gxstep;
            gxv = *(const float4*)&g_Gx[go];
        }

        if (tid == 0) {
            unsigned target = (unsigned)GRID_P * (unsigned)(t + 1);
            while (*(volatile unsigned*)&g_sync < target) { }
            __threadfence();
        }
        __syncthreads();
    }
}

// ---------------------------------------------------------------------------
extern "C" void kernel_launch(void* const* d_in, const int* in_sizes, int n_in,
                              void* d_out, int out_size) {
    const float* X  = (const float*)d_in[0];
    const float* Wf = (const float*)d_in[1];
    const float* bf = (const float*)d_in[2];
    const float* Wi = (const float*)d_in[3];
    const float* bi = (const float*)d_in[4];
    const float* Wg = (const float*)d_in[5];
    const float* bg = (const float*)d_in[6];
    const float* Wo = (const float*)d_in[7];
    const float* bo = (const float*)d_in[8];
    float* out = (float*)d_out;

    cudaFuncSetAttribute(lstm_persistent,
                         cudaFuncAttributeMaxDynamicSharedMemorySize, SMEM_TOTAL);
    cudaFuncSetAttribute(gemm_x_mma,
                         cudaFuncAttributeMaxDynamicSharedMemorySize, GX_SMEM);

    init_kernel<<<(BATCH * HID + 255) / 256, 256>>>(bf, bi, bg, bo);
    pack_kernel<<<dim3((DH - DIN) / 32, NG / 32), dim3(32, 32)>>>(Wf, Wi, Wg, Wo);
    wxpack_kernel<<<(NG * DIN / 4 + 255) / 256, 256>>>(Wf, Wi, Wg, Wo);
    xsplit_kernel<<<(M1 * DIN / 4 + 255) / 256, 256>>>(X);
    gemm_x_mma<<<dim3(NG / 64, M1 / 128), 256, GX_SMEM>>>(0);

    const long long OUT_MAIN = (long long)T_STEPS * BATCH * HID;
    int write_tail = ((long long)out_size >= OUT_MAIN + 2LL * BATCH * HID) ? 1 : 0;

    lstm_persistent<<<GRID_P, THR_R, SMEM_TOTAL>>>(out, write_tail);
}